// round 8
// baseline (speedup 1.0000x reference)
#include <cuda_runtime.h>

// SMFNet: out[i,:] = F[i,0]*V[i,:] + F[i,1]*V[(i+1)%N,:]
//   V = relu(X @ Wg^T), F = relu(X @ Wf^T),  X:[N,128], Wf,Wg:[2,128]
// Warp-per-row, 32 warps/block, 4 rows/warp => 128 rows/block.
// Neighbor V exchanged via shared; one extra (wrapped) row per block.

#define WARPS_PER_BLOCK 32
#define ROWS_PER_WARP   4
#define ROWS_PER_BLOCK  (WARPS_PER_BLOCK * ROWS_PER_WARP)  // 128
#define D_VEC           32                                  // 128 floats = 32 float4

__device__ __forceinline__ float dot4(float4 a, float4 b) {
    return fmaf(a.x, b.x, fmaf(a.y, b.y, fmaf(a.z, b.z, a.w * b.w)));
}

__global__ __launch_bounds__(1024, 1)
void smfnet_kernel(const float4* __restrict__ X,
                   const float4* __restrict__ Wf,
                   const float4* __restrict__ Wg,
                   float2* __restrict__ out,
                   int N) {
    __shared__ float2 sV[ROWS_PER_BLOCK + 1];

    const int tid  = threadIdx.x;
    const int wid  = tid >> 5;
    const int lane = tid & 31;

    // Per-lane weight slices: lane l holds elements [4l, 4l+4) of each weight row.
    const float4 wf0 = Wf[lane];
    const float4 wf1 = Wf[D_VEC + lane];
    const float4 wg0 = Wg[lane];
    const float4 wg1 = Wg[D_VEC + lane];

    const long long r0 = (long long)blockIdx.x * ROWS_PER_BLOCK;
    const int nrows = (int)min((long long)ROWS_PER_BLOCK, (long long)N - r0);

    const int base_lr = wid * ROWS_PER_WARP;

    // Issue all row loads first (MLP=4 per warp).
    float4 xv[ROWS_PER_WARP];
    #pragma unroll
    for (int it = 0; it < ROWS_PER_WARP; it++) {
        const int lr = base_lr + it;
        if (lr < nrows)
            xv[it] = X[(r0 + lr) * D_VEC + lane];
    }

    float f0[ROWS_PER_WARP], f1[ROWS_PER_WARP];

    #pragma unroll
    for (int it = 0; it < ROWS_PER_WARP; it++) {
        const int lr = base_lr + it;
        if (lr >= nrows) continue;   // warp-uniform (lr depends only on wid/it)

        float pf0 = dot4(xv[it], wf0);
        float pf1 = dot4(xv[it], wf1);
        float pg0 = dot4(xv[it], wg0);
        float pg1 = dot4(xv[it], wg1);

        #pragma unroll
        for (int off = 16; off > 0; off >>= 1) {
            pf0 += __shfl_xor_sync(0xffffffffu, pf0, off);
            pf1 += __shfl_xor_sync(0xffffffffu, pf1, off);
            pg0 += __shfl_xor_sync(0xffffffffu, pg0, off);
            pg1 += __shfl_xor_sync(0xffffffffu, pg1, off);
        }

        f0[it] = fmaxf(pf0, 0.0f);
        f1[it] = fmaxf(pf1, 0.0f);
        if (lane == 0)
            sV[lr] = make_float2(fmaxf(pg0, 0.0f), fmaxf(pg1, 0.0f));
    }

    // One extra V for the block's right boundary (wrapped): row (r0 + nrows) % N.
    if (wid == 0) {
        long long rext = r0 + nrows;
        if (rext >= N) rext -= N;
        const float4 xe = X[rext * D_VEC + lane];
        float pg0 = dot4(xe, wg0);
        float pg1 = dot4(xe, wg1);
        #pragma unroll
        for (int off = 16; off > 0; off >>= 1) {
            pg0 += __shfl_xor_sync(0xffffffffu, pg0, off);
            pg1 += __shfl_xor_sync(0xffffffffu, pg1, off);
        }
        if (lane == 0)
            sV[nrows] = make_float2(fmaxf(pg0, 0.0f), fmaxf(pg1, 0.0f));
    }

    __syncthreads();

    #pragma unroll
    for (int it = 0; it < ROWS_PER_WARP; it++) {
        const int lr = base_lr + it;
        if (lr < nrows && lane == 0) {
            const float2 v  = sV[lr];
            const float2 vn = sV[lr + 1];
            out[r0 + lr] = make_float2(fmaf(f0[it], v.x, f1[it] * vn.x),
                                       fmaf(f0[it], v.y, f1[it] * vn.y));
        }
    }
}

extern "C" void kernel_launch(void* const* d_in, const int* in_sizes, int n_in,
                              void* d_out, int out_size) {
    const float4* X  = (const float4*)d_in[0];   // [N,128] fp32
    const float4* Wf = (const float4*)d_in[1];   // [2,128] fp32
    const float4* Wg = (const float4*)d_in[2];   // [2,128] fp32
    float2* out = (float2*)d_out;                // [N,2] fp32

    const int N = in_sizes[0] / 128;
    const int grid = (N + ROWS_PER_BLOCK - 1) / ROWS_PER_BLOCK;

    smfnet_kernel<<<grid, WARPS_PER_BLOCK * 32>>>(X, Wf, Wg, out, N);
}

// round 9
// speedup vs baseline: 1.0045x; 1.0045x over previous
#include <cuda_runtime.h>

// SMFNet: out[i,:] = F[i,0]*V[i,:] + F[i,1]*V[(i+1)%N,:]
//   V = relu(X @ Wg^T), F = relu(X @ Wf^T),  X:[N,128], Wf,Wg:[2,128]
// Warp-per-row, 32 warps/block, 4 rows/warp => 128 rows/block.
// Neighbor V exchanged via shared; one extra (wrapped) row per block.

#define WARPS_PER_BLOCK 32
#define ROWS_PER_WARP   4
#define ROWS_PER_BLOCK  (WARPS_PER_BLOCK * ROWS_PER_WARP)  // 128
#define D_VEC           32                                  // 128 floats = 32 float4

__device__ __forceinline__ float dot4(float4 a, float4 b) {
    return fmaf(a.x, b.x, fmaf(a.y, b.y, fmaf(a.z, b.z, a.w * b.w)));
}

__global__ __launch_bounds__(1024, 1)
void smfnet_kernel(const float4* __restrict__ X,
                   const float4* __restrict__ Wf,
                   const float4* __restrict__ Wg,
                   float2* __restrict__ out,
                   int N) {
    __shared__ float2 sV[ROWS_PER_BLOCK + 1];

    const int tid  = threadIdx.x;
    const int wid  = tid >> 5;
    const int lane = tid & 31;

    // Per-lane weight slices: lane l holds elements [4l, 4l+4) of each weight row.
    const float4 wf0 = Wf[lane];
    const float4 wf1 = Wf[D_VEC + lane];
    const float4 wg0 = Wg[lane];
    const float4 wg1 = Wg[D_VEC + lane];

    const long long r0 = (long long)blockIdx.x * ROWS_PER_BLOCK;
    const int nrows = (int)min((long long)ROWS_PER_BLOCK, (long long)N - r0);

    const int base_lr = wid * ROWS_PER_WARP;

    // Issue all row loads first (MLP=4 per warp).
    float4 xv[ROWS_PER_WARP];
    #pragma unroll
    for (int it = 0; it < ROWS_PER_WARP; it++) {
        const int lr = base_lr + it;
        if (lr < nrows)
            xv[it] = X[(r0 + lr) * D_VEC + lane];
    }

    float f0[ROWS_PER_WARP], f1[ROWS_PER_WARP];

    #pragma unroll
    for (int it = 0; it < ROWS_PER_WARP; it++) {
        const int lr = base_lr + it;
        if (lr >= nrows) continue;   // warp-uniform (lr depends only on wid/it)

        float pf0 = dot4(xv[it], wf0);
        float pf1 = dot4(xv[it], wf1);
        float pg0 = dot4(xv[it], wg0);
        float pg1 = dot4(xv[it], wg1);

        #pragma unroll
        for (int off = 16; off > 0; off >>= 1) {
            pf0 += __shfl_xor_sync(0xffffffffu, pf0, off);
            pf1 += __shfl_xor_sync(0xffffffffu, pf1, off);
            pg0 += __shfl_xor_sync(0xffffffffu, pg0, off);
            pg1 += __shfl_xor_sync(0xffffffffu, pg1, off);
        }

        f0[it] = fmaxf(pf0, 0.0f);
        f1[it] = fmaxf(pf1, 0.0f);
        if (lane == 0)
            sV[lr] = make_float2(fmaxf(pg0, 0.0f), fmaxf(pg1, 0.0f));
    }

    // One extra V for the block's right boundary (wrapped): row (r0 + nrows) % N.
    if (wid == 0) {
        long long rext = r0 + nrows;
        if (rext >= N) rext -= N;
        const float4 xe = X[rext * D_VEC + lane];
        float pg0 = dot4(xe, wg0);
        float pg1 = dot4(xe, wg1);
        #pragma unroll
        for (int off = 16; off > 0; off >>= 1) {
            pg0 += __shfl_xor_sync(0xffffffffu, pg0, off);
            pg1 += __shfl_xor_sync(0xffffffffu, pg1, off);
        }
        if (lane == 0)
            sV[nrows] = make_float2(fmaxf(pg0, 0.0f), fmaxf(pg1, 0.0f));
    }

    __syncthreads();

    #pragma unroll
    for (int it = 0; it < ROWS_PER_WARP; it++) {
        const int lr = base_lr + it;
        if (lr < nrows && lane == 0) {
            const float2 v  = sV[lr];
            const float2 vn = sV[lr + 1];
            out[r0 + lr] = make_float2(fmaf(f0[it], v.x, f1[it] * vn.x),
                                       fmaf(f0[it], v.y, f1[it] * vn.y));
        }
    }
}

extern "C" void kernel_launch(void* const* d_in, const int* in_sizes, int n_in,
                              void* d_out, int out_size) {
    const float4* X  = (const float4*)d_in[0];   // [N,128] fp32
    const float4* Wf = (const float4*)d_in[1];   // [2,128] fp32
    const float4* Wg = (const float4*)d_in[2];   // [2,128] fp32
    float2* out = (float2*)d_out;                // [N,2] fp32

    const int N = in_sizes[0] / 128;
    const int grid = (N + ROWS_PER_BLOCK - 1) / ROWS_PER_BLOCK;

    smfnet_kernel<<<grid, WARPS_PER_BLOCK * 32>>>(X, Wf, Wg, out, N);
}

// round 10
// speedup vs baseline: 1.0123x; 1.0077x over previous
#include <cuda_runtime.h>

// SMFNet: out[i,:] = F[i,0]*V[i,:] + F[i,1]*V[(i+1)%N,:]
//   V = relu(X @ Wg^T), F = relu(X @ Wf^T),  X:[N,128], Wf,Wg:[2,128]
// Warp-per-row, 32 warps/block, 4 rows/warp => 128 rows/block.
// Neighbor V exchanged via shared; one extra (wrapped) row per block.

#define WARPS_PER_BLOCK 32
#define ROWS_PER_WARP   4
#define ROWS_PER_BLOCK  (WARPS_PER_BLOCK * ROWS_PER_WARP)  // 128
#define D_VEC           32                                  // 128 floats = 32 float4

__device__ __forceinline__ float dot4(float4 a, float4 b) {
    return fmaf(a.x, b.x, fmaf(a.y, b.y, fmaf(a.z, b.z, a.w * b.w)));
}

__global__ __launch_bounds__(1024, 1)
void smfnet_kernel(const float4* __restrict__ X,
                   const float4* __restrict__ Wf,
                   const float4* __restrict__ Wg,
                   float2* __restrict__ out,
                   int N) {
    __shared__ float2 sV[ROWS_PER_BLOCK + 1];

    const int tid  = threadIdx.x;
    const int wid  = tid >> 5;
    const int lane = tid & 31;

    // Per-lane weight slices: lane l holds elements [4l, 4l+4) of each weight row.
    const float4 wf0 = Wf[lane];
    const float4 wf1 = Wf[D_VEC + lane];
    const float4 wg0 = Wg[lane];
    const float4 wg1 = Wg[D_VEC + lane];

    const long long r0 = (long long)blockIdx.x * ROWS_PER_BLOCK;
    const int nrows = (int)min((long long)ROWS_PER_BLOCK, (long long)N - r0);

    const int base_lr = wid * ROWS_PER_WARP;

    // Issue all row loads first (MLP=4 per warp).
    float4 xv[ROWS_PER_WARP];
    #pragma unroll
    for (int it = 0; it < ROWS_PER_WARP; it++) {
        const int lr = base_lr + it;
        if (lr < nrows)
            xv[it] = X[(r0 + lr) * D_VEC + lane];
    }

    float f0[ROWS_PER_WARP], f1[ROWS_PER_WARP];

    #pragma unroll
    for (int it = 0; it < ROWS_PER_WARP; it++) {
        const int lr = base_lr + it;
        if (lr >= nrows) continue;   // warp-uniform (lr depends only on wid/it)

        float pf0 = dot4(xv[it], wf0);
        float pf1 = dot4(xv[it], wf1);
        float pg0 = dot4(xv[it], wg0);
        float pg1 = dot4(xv[it], wg1);

        #pragma unroll
        for (int off = 16; off > 0; off >>= 1) {
            pf0 += __shfl_xor_sync(0xffffffffu, pf0, off);
            pf1 += __shfl_xor_sync(0xffffffffu, pf1, off);
            pg0 += __shfl_xor_sync(0xffffffffu, pg0, off);
            pg1 += __shfl_xor_sync(0xffffffffu, pg1, off);
        }

        f0[it] = fmaxf(pf0, 0.0f);
        f1[it] = fmaxf(pf1, 0.0f);
        if (lane == 0)
            sV[lr] = make_float2(fmaxf(pg0, 0.0f), fmaxf(pg1, 0.0f));
    }

    // One extra V for the block's right boundary (wrapped): row (r0 + nrows) % N.
    if (wid == 0) {
        long long rext = r0 + nrows;
        if (rext >= N) rext -= N;
        const float4 xe = X[rext * D_VEC + lane];
        float pg0 = dot4(xe, wg0);
        float pg1 = dot4(xe, wg1);
        #pragma unroll
        for (int off = 16; off > 0; off >>= 1) {
            pg0 += __shfl_xor_sync(0xffffffffu, pg0, off);
            pg1 += __shfl_xor_sync(0xffffffffu, pg1, off);
        }
        if (lane == 0)
            sV[nrows] = make_float2(fmaxf(pg0, 0.0f), fmaxf(pg1, 0.0f));
    }

    __syncthreads();

    #pragma unroll
    for (int it = 0; it < ROWS_PER_WARP; it++) {
        const int lr = base_lr + it;
        if (lr < nrows && lane == 0) {
            const float2 v  = sV[lr];
            const float2 vn = sV[lr + 1];
            out[r0 + lr] = make_float2(fmaf(f0[it], v.x, f1[it] * vn.x),
                                       fmaf(f0[it], v.y, f1[it] * vn.y));
        }
    }
}

extern "C" void kernel_launch(void* const* d_in, const int* in_sizes, int n_in,
                              void* d_out, int out_size) {
    const float4* X  = (const float4*)d_in[0];   // [N,128] fp32
    const float4* Wf = (const float4*)d_in[1];   // [2,128] fp32
    const float4* Wg = (const float4*)d_in[2];   // [2,128] fp32
    float2* out = (float2*)d_out;                // [N,2] fp32

    const int N = in_sizes[0] / 128;
    const int grid = (N + ROWS_PER_BLOCK - 1) / ROWS_PER_BLOCK;

    smfnet_kernel<<<grid, WARPS_PER_BLOCK * 32>>>(X, Wf, Wg, out, N);
}